// round 15
// baseline (speedup 1.0000x reference)
#include <cuda_runtime.h>
#include <cuda_fp16.h>
#include <math.h>

#define BB 4
#define NN 8192
#define KK 32
#define BN (BB*NN)

// scratch (device globals; no allocation)
__device__ uint2   g_F1ab[BN*32];   // per point: {a-pair, b-pair} fp16 per group L
__device__ __half2 g_F1c[BN*32];
__device__ float   g_z[BN*64];
__device__ float   g_rh[BN*64];

__device__ __forceinline__ float lrelu(float v){ return v > 0.f ? v : 0.1f*v; }
__device__ __forceinline__ float sigm(float v){ return 1.f/(1.f+expf(-v)); }

// ---------------- tensor-core helpers (mma.sync HMMA) ----------------
__device__ __forceinline__ unsigned sm_u32(const void* p){
    return (unsigned)__cvta_generic_to_shared(p);
}
__device__ __forceinline__ void ldsm_x4(unsigned &r0, unsigned &r1, unsigned &r2, unsigned &r3,
                                        unsigned addr){
    asm volatile("ldmatrix.sync.aligned.m8n8.x4.shared.b16 {%0,%1,%2,%3}, [%4];"
        : "=r"(r0), "=r"(r1), "=r"(r2), "=r"(r3) : "r"(addr));
}
__device__ __forceinline__ void ldsm_x4_t(unsigned &r0, unsigned &r1, unsigned &r2, unsigned &r3,
                                          unsigned addr){
    asm volatile("ldmatrix.sync.aligned.m8n8.x4.trans.shared.b16 {%0,%1,%2,%3}, [%4];"
        : "=r"(r0), "=r"(r1), "=r"(r2), "=r"(r3) : "r"(addr));
}
__device__ __forceinline__ void mma16816(float* c,
        unsigned a0, unsigned a1, unsigned a2, unsigned a3,
        unsigned b0, unsigned b1){
    asm volatile("mma.sync.aligned.m16n8k16.row.col.f32.f16.f16.f32 "
        "{%0,%1,%2,%3}, {%4,%5,%6,%7}, {%8,%9}, {%0,%1,%2,%3};"
        : "+f"(c[0]), "+f"(c[1]), "+f"(c[2]), "+f"(c[3])
        : "r"(a0), "r"(a1), "r"(a2), "r"(a3), "r"(b0), "r"(b1));
}

#define ASTR 136
#define B2STR 136
#define B1STR 72
#define PSTR 72          // padded row stride (halfs) for 64-wide fp16 tiles

// ---------------- linear2 (HMMA): F1ab = [h|x] @ {W1a[0],W1a[1]} ----------------
__global__ void __launch_bounds__(256)
linear2_hmma(const float* __restrict__ s0, const float* __restrict__ s1,
             const float* __restrict__ W1, unsigned* __restrict__ out32)
{
    extern __shared__ __half smh[];
    __half* A = smh;                 // 64 x ASTR
    __half* B = smh + 64*ASTR;       // 128 x B2STR
    int tid = threadIdx.x, w = tid>>5, L = tid&31;
    int wm = w >> 1, wn = w & 1;     // 4 m-warps x 2 n-warps

    const float* Wa = W1;
    const float* Wb = W1 + 131*64;
    for (int i = tid; i < 128*64; i += 256) {
        int k = i >> 6, n = i & 63;
        B[k*B2STR + n]      = __float2half_rn(Wa[k*64 + n]);
        B[k*B2STR + 64 + n] = __float2half_rn(Wb[k*64 + n]);
    }
    __syncthreads();

    int r = L >> 2, cq = (L & 3) * 2;
    for (int tile = blockIdx.x; tile < BN/64; tile += gridDim.x) {
        int pt0 = tile * 64;
        for (int i = tid; i < 64*64; i += 256) {
            int p = i >> 6, c2 = i & 63;
            float2 v = (c2 < 32) ? *(const float2*)&s0[(size_t)(pt0+p)*64 + 2*c2]
                                 : *(const float2*)&s1[(size_t)(pt0+p)*64 + 2*(c2-32)];
            *(__half2*)&A[p*ASTR + 2*c2] = __floats2half2_rn(v.x, v.y);
        }
        __syncthreads();

        float C[8][4];
        #pragma unroll
        for (int i = 0; i < 8; i++)
            #pragma unroll
            for (int j = 0; j < 4; j++) C[i][j] = 0.f;

        #pragma unroll
        for (int ks = 0; ks < 8; ks++) {
            int k0 = ks * 16;
            unsigned a0,a1,a2,a3;
            ldsm_x4(a0,a1,a2,a3, sm_u32(&A[(wm*16 + (L&15))*ASTR + k0 + (L>>4)*8]));
            #pragma unroll
            for (int nt = 0; nt < 4; nt++) {
                unsigned b0,b1,b2,b3;
                ldsm_x4_t(b0,b1,b2,b3,
                    sm_u32(&B[(k0 + (L&15))*B2STR + wn*64 + nt*16 + (L>>4)*8]));
                mma16816(C[2*nt],   a0,a1,a2,a3, b0,b1);
                mma16816(C[2*nt+1], a0,a1,a2,a3, b2,b3);
            }
        }
        #pragma unroll
        for (int nt8 = 0; nt8 < 8; nt8++) {
            int col = wn*64 + nt8*8 + cq;
            int oidx = (col < 64) ? col : (col - 63);
            int p = pt0 + wm*16 + r;
            __half2 lo = __floats2half2_rn(C[nt8][0], C[nt8][1]);
            __half2 hi = __floats2half2_rn(C[nt8][2], C[nt8][3]);
            out32[(size_t)p*64 + oidx]     = *(const unsigned*)&lo;
            out32[(size_t)(p+8)*64 + oidx] = *(const unsigned*)&hi;
        }
        __syncthreads();
    }
}

// ---------------- linear1 (HMMA): F1c = [rh|x] @ W1a[2] ----------------
__global__ void __launch_bounds__(256)
linear1_hmma(const float* __restrict__ s0, const float* __restrict__ s1,
             const float* __restrict__ W1, unsigned* __restrict__ out32)
{
    extern __shared__ __half smh[];
    __half* A = smh;
    __half* B = smh + 64*ASTR;
    int tid = threadIdx.x, w = tid>>5, L = tid&31;
    int wm = w >> 1, wn = w & 1;

    const float* Wc = W1 + 2*131*64;
    for (int i = tid; i < 128*64; i += 256) {
        int k = i >> 6, n = i & 63;
        B[k*B1STR + n] = __float2half_rn(Wc[k*64 + n]);
    }
    __syncthreads();

    int r = L >> 2, cq = (L & 3) * 2;
    for (int tile = blockIdx.x; tile < BN/64; tile += gridDim.x) {
        int pt0 = tile * 64;
        for (int i = tid; i < 64*64; i += 256) {
            int p = i >> 6, c2 = i & 63;
            float2 v = (c2 < 32) ? *(const float2*)&s0[(size_t)(pt0+p)*64 + 2*c2]
                                 : *(const float2*)&s1[(size_t)(pt0+p)*64 + 2*(c2-32)];
            *(__half2*)&A[p*ASTR + 2*c2] = __floats2half2_rn(v.x, v.y);
        }
        __syncthreads();

        float C[4][4];
        #pragma unroll
        for (int i = 0; i < 4; i++)
            #pragma unroll
            for (int j = 0; j < 4; j++) C[i][j] = 0.f;

        #pragma unroll
        for (int ks = 0; ks < 8; ks++) {
            int k0 = ks * 16;
            unsigned a0,a1,a2,a3;
            ldsm_x4(a0,a1,a2,a3, sm_u32(&A[(wm*16 + (L&15))*ASTR + k0 + (L>>4)*8]));
            #pragma unroll
            for (int nt = 0; nt < 2; nt++) {
                unsigned b0,b1,b2,b3;
                ldsm_x4_t(b0,b1,b2,b3,
                    sm_u32(&B[(k0 + (L&15))*B1STR + wn*32 + nt*16 + (L>>4)*8]));
                mma16816(C[2*nt],   a0,a1,a2,a3, b0,b1);
                mma16816(C[2*nt+1], a0,a1,a2,a3, b2,b3);
            }
        }
        #pragma unroll
        for (int nt8 = 0; nt8 < 4; nt8++) {
            int col = wn*32 + nt8*8 + cq;
            int p = pt0 + wm*16 + r;
            __half2 lo = __floats2half2_rn(C[nt8][0], C[nt8][1]);
            __half2 hi = __floats2half2_rn(C[nt8][2], C[nt8][3]);
            out32[(size_t)p*32 + (col>>1)]     = *(const unsigned*)&lo;
            out32[(size_t)(p+8)*32 + (col>>1)] = *(const unsigned*)&hi;
        }
        __syncthreads();
    }
}

// ---------------- gate01 (HMMA MLP): branches 0+1 -> z, r*h ----------------
// tile = 64 points, 8 warps: gather 8 pts/warp (2-pt interleaved), HMMA MLP.
__global__ void __launch_bounds__(256)
gate01_hmma(const float* __restrict__ h,
    const float* __restrict__ W1, const float* __restrict__ b1,
    const float* __restrict__ W2, const float* __restrict__ b2,
    const float* __restrict__ W3, const float* __restrict__ b3,
    const int* __restrict__ nidx, const float* __restrict__ ef,
    float* __restrict__ z_out, float* __restrict__ rh_out)
{
    extern __shared__ __half smh[];
    __half* sW2 = smh;                 // 2 x [64 x PSTR]
    __half* sW3 = smh + 2*64*PSTR;     // 2 x [64 x PSTR]
    __half* P   = smh + 4*64*PSTR;     // 2 x [64 x PSTR]  (PA, PB)
    uint2* mt_all = (uint2*)(smh + 6*64*PSTR);  // 8 warps x 64 uint2
    int tid = threadIdx.x, w = tid>>5, L = tid&31;

    for (int i = tid; i < 2*64*64; i += 256) {
        int br = i >> 12, rem = i & 4095, j = rem >> 6, d = rem & 63;
        sW2[br*64*PSTR + j*PSTR + d] = __float2half_rn(W2[br*4096 + j*64 + d]);
        sW3[br*64*PSTR + j*PSTR + d] = __float2half_rn(W3[br*4096 + j*64 + d]);
    }
    __syncthreads();

    const float* eWa = W1 + 128*64;
    const float* eWb = W1 + 131*64 + 128*64;
    __half2 wA[3], wB[3];
    #pragma unroll
    for (int j = 0; j < 3; j++) {
        wA[j] = __floats2half2_rn(eWa[j*64 + 2*L], eWa[j*64 + 2*L + 1]);
        wB[j] = __floats2half2_rn(eWb[j*64 + 2*L], eWb[j*64 + 2*L + 1]);
    }
    float2 b1a = *(const float2*)&b1[2*L], b1b = *(const float2*)&b1[64 + 2*L];

    int pt0 = blockIdx.x * 64;
    int bb = pt0 >> 13;
    const uint2* Fab = g_F1ab + (size_t)bb*NN*32;
    __half* PA = P;
    __half* PB = P + 64*PSTR;
    uint2* mt0 = mt_all + w*64;
    uint2* mt1 = mt0 + 32;

    // ---- phase 1: gather + pool, 2 points interleaved ----
    for (int qq = 0; qq < 4; qq++) {
        int pl0 = w*8 + 2*qq, pl1 = pl0 + 1;
        int pA = pt0 + pl0, pB = pt0 + pl1;
        {
            int fiA = nidx[(size_t)pA*KK + L];
            const float* epA = ef + (size_t)pA*96 + 3*L;
            __half2 ea01 = __floats2half2_rn(epA[0], epA[1]);
            unsigned ea2 = (unsigned)__half_as_ushort(__float2half_rn(epA[2]));
            mt0[L] = make_uint2((unsigned)fiA | (ea2 << 16), *(const unsigned*)&ea01);
            int fiB = nidx[(size_t)pB*KK + L];
            const float* epB = ef + (size_t)pB*96 + 3*L;
            __half2 eb01 = __floats2half2_rn(epB[0], epB[1]);
            unsigned eb2 = (unsigned)__half_as_ushort(__float2half_rn(epB[2]));
            mt1[L] = make_uint2((unsigned)fiB | (eb2 << 16), *(const unsigned*)&eb01);
        }
        __syncwarp();
        __half2 ma0 = __float2half2_rn(-6.0e4f), mb0 = ma0;
        __half2 ma1 = ma0, mb1 = ma0;
        #pragma unroll 8
        for (int k = 0; k < KK; k++) {
            uint2 m0 = mt0[k];
            uint2 m1 = mt1[k];
            uint2 v0 = __ldg(&Fab[(size_t)(m0.x & 0xFFFFu)*32 + L]);
            uint2 v1 = __ldg(&Fab[(size_t)(m1.x & 0xFFFFu)*32 + L]);
            // point 0
            {
                __half2 h2v = __half2half2(__ushort_as_half((unsigned short)(m0.x >> 16)));
                __half2 e01 = *(const __half2*)&m0.y;
                __half2 h0 = __low2half2(e01), h1 = __high2half2(e01);
                __half2 ta = *(const __half2*)&v0.x;
                ta = __hfma2(h0, wA[0], ta);
                ta = __hfma2(h1, wA[1], ta);
                ta = __hfma2(h2v, wA[2], ta);
                ma0 = __hmax2(ma0, ta);
                __half2 tb = *(const __half2*)&v0.y;
                tb = __hfma2(h0, wB[0], tb);
                tb = __hfma2(h1, wB[1], tb);
                tb = __hfma2(h2v, wB[2], tb);
                mb0 = __hmax2(mb0, tb);
            }
            // point 1
            {
                __half2 h2v = __half2half2(__ushort_as_half((unsigned short)(m1.x >> 16)));
                __half2 e01 = *(const __half2*)&m1.y;
                __half2 h0 = __low2half2(e01), h1 = __high2half2(e01);
                __half2 ta = *(const __half2*)&v1.x;
                ta = __hfma2(h0, wA[0], ta);
                ta = __hfma2(h1, wA[1], ta);
                ta = __hfma2(h2v, wA[2], ta);
                ma1 = __hmax2(ma1, ta);
                __half2 tb = *(const __half2*)&v1.y;
                tb = __hfma2(h0, wB[0], tb);
                tb = __hfma2(h1, wB[1], tb);
                tb = __hfma2(h2v, wB[2], tb);
                mb1 = __hmax2(mb1, tb);
            }
        }
        __syncwarp();
        float2 fa0 = __half22float2(ma0), fb0 = __half22float2(mb0);
        float2 fa1 = __half22float2(ma1), fb1 = __half22float2(mb1);
        fa0.x = lrelu(fa0.x + b1a.x);  fa0.y = lrelu(fa0.y + b1a.y);
        fb0.x = lrelu(fb0.x + b1b.x);  fb0.y = lrelu(fb0.y + b1b.y);
        fa1.x = lrelu(fa1.x + b1a.x);  fa1.y = lrelu(fa1.y + b1a.y);
        fb1.x = lrelu(fb1.x + b1b.x);  fb1.y = lrelu(fb1.y + b1b.y);
        *(__half2*)&PA[pl0*PSTR + 2*L] = __floats2half2_rn(fa0.x, fa0.y);
        *(__half2*)&PB[pl0*PSTR + 2*L] = __floats2half2_rn(fb0.x, fb0.y);
        *(__half2*)&PA[pl1*PSTR + 2*L] = __floats2half2_rn(fa1.x, fa1.y);
        *(__half2*)&PB[pl1*PSTR + 2*L] = __floats2half2_rn(fb1.x, fb1.y);
    }
    __syncthreads();

    // ---- phase 2: MLP on tensor pipe ----
    int wbr = w >> 2, wm = w & 3;        // 4 m-warps per branch
    __half* Pb  = P   + wbr*64*PSTR;
    __half* W2b = sW2 + wbr*64*PSTR;
    __half* W3b = sW3 + wbr*64*PSTR;
    int r = L >> 2, cq = (L & 3) * 2;
    const float* b2v = b2 + wbr*64;
    const float* b3v = b3 + wbr*64;

    // layer 1
    float C[8][4];
    #pragma unroll
    for (int i = 0; i < 8; i++)
        #pragma unroll
        for (int j = 0; j < 4; j++) C[i][j] = 0.f;
    #pragma unroll
    for (int ks = 0; ks < 4; ks++) {
        int k0 = ks * 16;
        unsigned a0,a1,a2,a3;
        ldsm_x4(a0,a1,a2,a3, sm_u32(&Pb[(wm*16 + (L&15))*PSTR + k0 + (L>>4)*8]));
        #pragma unroll
        for (int nt = 0; nt < 4; nt++) {
            unsigned b0v,b1v,b2q,b3q;
            ldsm_x4_t(b0v,b1v,b2q,b3q,
                sm_u32(&W2b[(k0 + (L&15))*PSTR + nt*16 + (L>>4)*8]));
            mma16816(C[2*nt],   a0,a1,a2,a3, b0v,b1v);
            mma16816(C[2*nt+1], a0,a1,a2,a3, b2q,b3q);
        }
    }
    __syncthreads();   // all ldsm of P complete -> safe to overwrite
    #pragma unroll
    for (int nt8 = 0; nt8 < 8; nt8++) {
        int col = nt8*8 + cq;
        float c0 = lrelu(C[nt8][0] + __ldg(&b2v[col]));
        float c1 = lrelu(C[nt8][1] + __ldg(&b2v[col+1]));
        float c2 = lrelu(C[nt8][2] + __ldg(&b2v[col]));
        float c3 = lrelu(C[nt8][3] + __ldg(&b2v[col+1]));
        *(__half2*)&Pb[(wm*16 + r)*PSTR + col]     = __floats2half2_rn(c0, c1);
        *(__half2*)&Pb[(wm*16 + r + 8)*PSTR + col] = __floats2half2_rn(c2, c3);
    }
    __syncthreads();

    // layer 2
    #pragma unroll
    for (int i = 0; i < 8; i++)
        #pragma unroll
        for (int j = 0; j < 4; j++) C[i][j] = 0.f;
    #pragma unroll
    for (int ks = 0; ks < 4; ks++) {
        int k0 = ks * 16;
        unsigned a0,a1,a2,a3;
        ldsm_x4(a0,a1,a2,a3, sm_u32(&Pb[(wm*16 + (L&15))*PSTR + k0 + (L>>4)*8]));
        #pragma unroll
        for (int nt = 0; nt < 4; nt++) {
            unsigned b0v,b1v,b2q,b3q;
            ldsm_x4_t(b0v,b1v,b2q,b3q,
                sm_u32(&W3b[(k0 + (L&15))*PSTR + nt*16 + (L>>4)*8]));
            mma16816(C[2*nt],   a0,a1,a2,a3, b0v,b1v);
            mma16816(C[2*nt+1], a0,a1,a2,a3, b2q,b3q);
        }
    }
    // final epilogue
    #pragma unroll
    for (int nt8 = 0; nt8 < 8; nt8++) {
        int col = nt8*8 + cq;
        int pLo = pt0 + wm*16 + r;
        int pHi = pLo + 8;
        float c0 = sigm(C[nt8][0] + __ldg(&b3v[col]));
        float c1 = sigm(C[nt8][1] + __ldg(&b3v[col+1]));
        float c2 = sigm(C[nt8][2] + __ldg(&b3v[col]));
        float c3 = sigm(C[nt8][3] + __ldg(&b3v[col+1]));
        if (wbr == 0) {
            *(float2*)&z_out[(size_t)pLo*64 + col] = make_float2(c0, c1);
            *(float2*)&z_out[(size_t)pHi*64 + col] = make_float2(c2, c3);
        } else {
            float2 hLo = *(const float2*)&h[(size_t)pLo*64 + col];
            float2 hHi = *(const float2*)&h[(size_t)pHi*64 + col];
            *(float2*)&rh_out[(size_t)pLo*64 + col] = make_float2(c0*hLo.x, c1*hLo.y);
            *(float2*)&rh_out[(size_t)pHi*64 + col] = make_float2(c2*hHi.x, c3*hHi.y);
        }
    }
}

// ---------------- gate2 (HMMA MLP): branch 2 -> q; out = h + z*(q-h) ----------------
// tile = 64 points, 8 warps: gather 8 pts/warp (2-pt interleaved), MLP 4x2.
__global__ void __launch_bounds__(256)
gate2_hmma(const float* __restrict__ h,
    const float* __restrict__ W1, const float* __restrict__ b1,
    const float* __restrict__ W2, const float* __restrict__ b2,
    const float* __restrict__ W3, const float* __restrict__ b3,
    const int* __restrict__ nidx, const float* __restrict__ ef,
    float* __restrict__ out)
{
    extern __shared__ __half smh[];
    __half* sW2 = smh;                 // [64 x PSTR]
    __half* sW3 = smh + 64*PSTR;       // [64 x PSTR]
    __half* P   = smh + 2*64*PSTR;     // [64 x PSTR]
    uint2* mt_all = (uint2*)(smh + 3*64*PSTR);  // 8 warps x 64 uint2
    int tid = threadIdx.x, w = tid>>5, L = tid&31;

    for (int i = tid; i < 64*64; i += 256) {
        int j = i >> 6, d = i & 63;
        sW2[j*PSTR + d] = __float2half_rn(W2[2*4096 + j*64 + d]);
        sW3[j*PSTR + d] = __float2half_rn(W3[2*4096 + j*64 + d]);
    }
    __syncthreads();

    const float* eWc = W1 + 2*131*64 + 128*64;
    __half2 wC[3];
    #pragma unroll
    for (int j = 0; j < 3; j++)
        wC[j] = __floats2half2_rn(eWc[j*64 + 2*L], eWc[j*64 + 2*L + 1]);
    float2 b1c = *(const float2*)&b1[128 + 2*L];

    int pt0 = blockIdx.x * 64;
    int bb = pt0 >> 13;
    const __half2* Fc = g_F1c + (size_t)bb*NN*32;
    uint2* mt0 = mt_all + w*64;
    uint2* mt1 = mt0 + 32;

    // ---- phase 1: gather + pool, 2 points interleaved ----
    for (int qq = 0; qq < 4; qq++) {
        int pl0 = w*8 + 2*qq, pl1 = pl0 + 1;
        int pA = pt0 + pl0, pB = pt0 + pl1;
        {
            int fiA = nidx[(size_t)pA*KK + L];
            const float* epA = ef + (size_t)pA*96 + 3*L;
            __half2 ea01 = __floats2half2_rn(epA[0], epA[1]);
            unsigned ea2 = (unsigned)__half_as_ushort(__float2half_rn(epA[2]));
            mt0[L] = make_uint2((unsigned)fiA | (ea2 << 16), *(const unsigned*)&ea01);
            int fiB = nidx[(size_t)pB*KK + L];
            const float* epB = ef + (size_t)pB*96 + 3*L;
            __half2 eb01 = __floats2half2_rn(epB[0], epB[1]);
            unsigned eb2 = (unsigned)__half_as_ushort(__float2half_rn(epB[2]));
            mt1[L] = make_uint2((unsigned)fiB | (eb2 << 16), *(const unsigned*)&eb01);
        }
        __syncwarp();
        __half2 mc0 = __float2half2_rn(-6.0e4f), mc1 = mc0;
        #pragma unroll 8
        for (int k = 0; k < KK; k++) {
            uint2 m0 = mt0[k];
            uint2 m1 = mt1[k];
            __half2 v0 = __ldg(&Fc[(size_t)(m0.x & 0xFFFFu)*32 + L]);
            __half2 v1 = __ldg(&Fc[(size_t)(m1.x & 0xFFFFu)*32 + L]);
            {
                __half2 h2v = __half2half2(__ushort_as_half((unsigned short)(m0.x >> 16)));
                __half2 e01 = *(const __half2*)&m0.y;
                __half2 h0 = __low2half2(e01), h1 = __high2half2(e01);
                v0 = __hfma2(h0, wC[0], v0);
                v0 = __hfma2(h1, wC[1], v0);
                v0 = __hfma2(h2v, wC[2], v0);
                mc0 = __hmax2(mc0, v0);
            }
            {
                __half2 h2v = __half2half2(__ushort_as_half((unsigned short)(m1.x >> 16)));
                __half2 e01 = *(const __half2*)&m1.y;
                __half2 h0 = __low2half2(e01), h1 = __high2half2(e01);
                v1 = __hfma2(h0, wC[0], v1);
                v1 = __hfma2(h1, wC[1], v1);
                v1 = __hfma2(h2v, wC[2], v1);
                mc1 = __hmax2(mc1, v1);
            }
        }
        __syncwarp();
        float2 fc0 = __half22float2(mc0), fc1 = __half22float2(mc1);
        fc0.x = lrelu(fc0.x + b1c.x);  fc0.y = lrelu(fc0.y + b1c.y);
        fc1.x = lrelu(fc1.x + b1c.x);  fc1.y = lrelu(fc1.y + b1c.y);
        *(__half2*)&P[pl0*PSTR + 2*L] = __floats2half2_rn(fc0.x, fc0.y);
        *(__half2*)&P[pl1*PSTR + 2*L] = __floats2half2_rn(fc1.x, fc1.y);
    }
    __syncthreads();

    // ---- phase 2: MLP (M=64, 4 m-bands x 2 n-halves over 8 warps) ----
    int wm = w >> 1, wn = w & 1;
    int r = L >> 2, cq = (L & 3) * 2;
    const float* b2v = b2 + 128;
    const float* b3v = b3 + 128;

    float C[4][4];
    #pragma unroll
    for (int i = 0; i < 4; i++)
        #pragma unroll
        for (int j = 0; j < 4; j++) C[i][j] = 0.f;
    #pragma unroll
    for (int ks = 0; ks < 4; ks++) {
        int k0 = ks * 16;
        unsigned a0,a1,a2,a3;
        ldsm_x4(a0,a1,a2,a3, sm_u32(&P[(wm*16 + (L&15))*PSTR + k0 + (L>>4)*8]));
        #pragma unroll
        for (int nt = 0; nt < 2; nt++) {
            unsigned b0v,b1v,b2q,b3q;
            ldsm_x4_t(b0v,b1v,b2q,b3q,
                sm_u32(&sW2[(k0 + (L&15))*PSTR + wn*32 + nt*16 + (L>>4)*8]));
            mma16816(C[2*nt],   a0,a1,a2,a3, b0v,b1v);
            mma16816(C[2*nt+1], a0,a1,a2,a3, b2q,b3q);
        }
    }
    __syncthreads();
    #pragma unroll
    for (int nt4 = 0; nt4 < 4; nt4++) {
        int col = wn*32 + nt4*8 + cq;
        float c0 = lrelu(C[nt4][0] + __ldg(&b2v[col]));
        float c1 = lrelu(C[nt4][1] + __ldg(&b2v[col+1]));
        float c2 = lrelu(C[nt4][2] + __ldg(&b2v[col]));
        float c3 = lrelu(C[nt4][3] + __ldg(&b2v[col+1]));
        *(__half2*)&P[(wm*16 + r)*PSTR + col]     = __floats2half2_rn(c0, c1);
        *(__half2*)&P[(wm*16 + r + 8)*PSTR + col] = __floats2half2_rn(c2, c3);
    }
    __syncthreads();

    #pragma unroll
    for (int i = 0; i < 4; i++)
        #pragma unroll
        for (int j = 0; j < 4; j++) C[i][j] = 0.f;
    #pragma unroll
    for (int ks = 0; ks < 4; ks++) {
        int k0 = ks * 16;
        unsigned a0,a1,a2,a3;
        ldsm_x4(a0,a1,a2,a3, sm_u32(&P[(wm*16 + (L&15))*PSTR + k0 + (L>>4)*8]));
        #pragma unroll
        for (int nt = 0; nt < 2; nt++) {
            unsigned b0v,b1v,b2q,b3q;
            ldsm_x4_t(b0v,b1v,b2q,b3q,
                sm_u32(&sW3[(k0 + (L&15))*PSTR + wn*32 + nt*16 + (L>>4)*8]));
            mma16816(C[2*nt],   a0,a1,a2,a3, b0v,b1v);
            mma16816(C[2*nt+1], a0,a1,a2,a3, b2q,b3q);
        }
    }
    #pragma unroll
    for (int nt4 = 0; nt4 < 4; nt4++) {
        int col = wn*32 + nt4*8 + cq;
        int pLo = pt0 + wm*16 + r;
        int pHi = pLo + 8;
        float q0 = tanhf(C[nt4][0] + __ldg(&b3v[col]));
        float q1 = tanhf(C[nt4][1] + __ldg(&b3v[col+1]));
        float q2 = tanhf(C[nt4][2] + __ldg(&b3v[col]));
        float q3 = tanhf(C[nt4][3] + __ldg(&b3v[col+1]));
        float2 zLo = *(const float2*)&g_z[(size_t)pLo*64 + col];
        float2 zHi = *(const float2*)&g_z[(size_t)pHi*64 + col];
        float2 hLo = *(const float2*)&h[(size_t)pLo*64 + col];
        float2 hHi = *(const float2*)&h[(size_t)pHi*64 + col];
        *(float2*)&out[(size_t)pLo*64 + col] =
            make_float2(hLo.x + zLo.x*(q0 - hLo.x), hLo.y + zLo.y*(q1 - hLo.y));
        *(float2*)&out[(size_t)pHi*64 + col] =
            make_float2(hHi.x + zHi.x*(q2 - hHi.x), hHi.y + zHi.y*(q3 - hHi.y));
    }
}

extern "C" void kernel_launch(void* const* d_in, const int* in_sizes, int n_in,
                              void* d_out, int out_size)
{
    const float* h   = (const float*)d_in[0];
    const float* x   = (const float*)d_in[1];
    // d_in[2] = c, unused (matches reference)
    const float* W1  = (const float*)d_in[3];
    const float* b1  = (const float*)d_in[4];
    const float* W2  = (const float*)d_in[5];
    const float* b2  = (const float*)d_in[6];
    const float* W3  = (const float*)d_in[7];
    const float* b3  = (const float*)d_in[8];
    const int*   nidx = (const int*)d_in[9];
    const float* ef  = (const float*)d_in[10];
    float* out = (float*)d_out;

    void *pF1ab, *pF1c, *pz, *prh;
    cudaGetSymbolAddress(&pF1ab, g_F1ab);
    cudaGetSymbolAddress(&pF1c,  g_F1c);
    cudaGetSymbolAddress(&pz,    g_z);
    cudaGetSymbolAddress(&prh,   g_rh);

    const int smem_l2h = (64*ASTR + 128*B2STR) * 2;        // 52224 B
    const int smem_l1h = (64*ASTR + 128*B1STR) * 2;        // 35840 B
    const int smem_g01 = 6*64*PSTR*2 + 8*64*8;             // 59392 B
    const int smem_g2  = 3*64*PSTR*2 + 8*64*8;             // 31744 B

    cudaFuncSetAttribute(linear2_hmma, cudaFuncAttributeMaxDynamicSharedMemorySize, smem_l2h);
    cudaFuncSetAttribute(linear1_hmma, cudaFuncAttributeMaxDynamicSharedMemorySize, smem_l1h);
    cudaFuncSetAttribute(gate01_hmma,  cudaFuncAttributeMaxDynamicSharedMemorySize, smem_g01);
    cudaFuncSetAttribute(gate2_hmma,   cudaFuncAttributeMaxDynamicSharedMemorySize, smem_g2);

    dim3 blk(256);

    // F1ab = [h|x] @ {W1a[0], W1a[1]}  (HMMA, packed fp16 out)
    linear2_hmma<<<296, blk, smem_l2h>>>(h, x, W1, (unsigned*)pF1ab);
    // z, r*h  (512 tiles of 64 points)
    gate01_hmma<<<512, blk, smem_g01>>>(h, W1, b1, W2, b2, W3, b3, nidx, ef,
                                        (float*)pz, (float*)prh);
    // F1c = [r*h|x] @ W1a[2]  (HMMA, fp16 out)
    linear1_hmma<<<296, blk, smem_l1h>>>((const float*)prh, x, W1, (unsigned*)pF1c);
    // q and final output  (512 tiles of 64 points)
    gate2_hmma<<<512, blk, smem_g2>>>(h, W1, b1, W2, b2, W3, b3, nidx, ef, out);
}

// round 16
// speedup vs baseline: 1.0793x; 1.0793x over previous
#include <cuda_runtime.h>
#include <cuda_fp16.h>
#include <math.h>

#define BB 4
#define NN 8192
#define KK 32
#define BN (BB*NN)

// scratch (device globals; no allocation)
__device__ uint2   g_F1ab[BN*32];   // per point: {a-pair, b-pair} fp16 per group L
__device__ __half2 g_F1c[BN*32];
__device__ float   g_z[BN*64];
__device__ float   g_rh[BN*64];

__device__ __forceinline__ float lrelu(float v){ return v > 0.f ? v : 0.1f*v; }
__device__ __forceinline__ float sigm(float v){ return 1.f/(1.f+expf(-v)); }

// ---------------- tensor-core helpers (mma.sync HMMA) ----------------
__device__ __forceinline__ unsigned sm_u32(const void* p){
    return (unsigned)__cvta_generic_to_shared(p);
}
__device__ __forceinline__ void ldsm_x4(unsigned &r0, unsigned &r1, unsigned &r2, unsigned &r3,
                                        unsigned addr){
    asm volatile("ldmatrix.sync.aligned.m8n8.x4.shared.b16 {%0,%1,%2,%3}, [%4];"
        : "=r"(r0), "=r"(r1), "=r"(r2), "=r"(r3) : "r"(addr));
}
__device__ __forceinline__ void ldsm_x4_t(unsigned &r0, unsigned &r1, unsigned &r2, unsigned &r3,
                                          unsigned addr){
    asm volatile("ldmatrix.sync.aligned.m8n8.x4.trans.shared.b16 {%0,%1,%2,%3}, [%4];"
        : "=r"(r0), "=r"(r1), "=r"(r2), "=r"(r3) : "r"(addr));
}
__device__ __forceinline__ void mma16816(float* c,
        unsigned a0, unsigned a1, unsigned a2, unsigned a3,
        unsigned b0, unsigned b1){
    asm volatile("mma.sync.aligned.m16n8k16.row.col.f32.f16.f16.f32 "
        "{%0,%1,%2,%3}, {%4,%5,%6,%7}, {%8,%9}, {%0,%1,%2,%3};"
        : "+f"(c[0]), "+f"(c[1]), "+f"(c[2]), "+f"(c[3])
        : "r"(a0), "r"(a1), "r"(a2), "r"(a3), "r"(b0), "r"(b1));
}

#define ASTR 136
#define B2STR 136
#define B1STR 72
#define PSTR 72          // padded row stride (halfs) for 64-wide fp16 tiles

// ---------------- linear2 (HMMA): F1ab = [h|x] @ {W1a[0],W1a[1]} ----------------
__global__ void __launch_bounds__(256)
linear2_hmma(const float* __restrict__ s0, const float* __restrict__ s1,
             const float* __restrict__ W1, unsigned* __restrict__ out32)
{
    extern __shared__ __half smh[];
    __half* A = smh;                 // 64 x ASTR
    __half* B = smh + 64*ASTR;       // 128 x B2STR
    int tid = threadIdx.x, w = tid>>5, L = tid&31;
    int wm = w >> 1, wn = w & 1;     // 4 m-warps x 2 n-warps

    const float* Wa = W1;
    const float* Wb = W1 + 131*64;
    for (int i = tid; i < 128*64; i += 256) {
        int k = i >> 6, n = i & 63;
        B[k*B2STR + n]      = __float2half_rn(Wa[k*64 + n]);
        B[k*B2STR + 64 + n] = __float2half_rn(Wb[k*64 + n]);
    }
    __syncthreads();

    int r = L >> 2, cq = (L & 3) * 2;
    for (int tile = blockIdx.x; tile < BN/64; tile += gridDim.x) {
        int pt0 = tile * 64;
        for (int i = tid; i < 64*64; i += 256) {
            int p = i >> 6, c2 = i & 63;
            float2 v = (c2 < 32) ? *(const float2*)&s0[(size_t)(pt0+p)*64 + 2*c2]
                                 : *(const float2*)&s1[(size_t)(pt0+p)*64 + 2*(c2-32)];
            *(__half2*)&A[p*ASTR + 2*c2] = __floats2half2_rn(v.x, v.y);
        }
        __syncthreads();

        float C[8][4];
        #pragma unroll
        for (int i = 0; i < 8; i++)
            #pragma unroll
            for (int j = 0; j < 4; j++) C[i][j] = 0.f;

        #pragma unroll
        for (int ks = 0; ks < 8; ks++) {
            int k0 = ks * 16;
            unsigned a0,a1,a2,a3;
            ldsm_x4(a0,a1,a2,a3, sm_u32(&A[(wm*16 + (L&15))*ASTR + k0 + (L>>4)*8]));
            #pragma unroll
            for (int nt = 0; nt < 4; nt++) {
                unsigned b0,b1,b2,b3;
                ldsm_x4_t(b0,b1,b2,b3,
                    sm_u32(&B[(k0 + (L&15))*B2STR + wn*64 + nt*16 + (L>>4)*8]));
                mma16816(C[2*nt],   a0,a1,a2,a3, b0,b1);
                mma16816(C[2*nt+1], a0,a1,a2,a3, b2,b3);
            }
        }
        #pragma unroll
        for (int nt8 = 0; nt8 < 8; nt8++) {
            int col = wn*64 + nt8*8 + cq;
            int oidx = (col < 64) ? col : (col - 63);
            int p = pt0 + wm*16 + r;
            __half2 lo = __floats2half2_rn(C[nt8][0], C[nt8][1]);
            __half2 hi = __floats2half2_rn(C[nt8][2], C[nt8][3]);
            out32[(size_t)p*64 + oidx]     = *(const unsigned*)&lo;
            out32[(size_t)(p+8)*64 + oidx] = *(const unsigned*)&hi;
        }
        __syncthreads();
    }
}

// ---------------- linear1 (HMMA): F1c = [rh|x] @ W1a[2] ----------------
__global__ void __launch_bounds__(256)
linear1_hmma(const float* __restrict__ s0, const float* __restrict__ s1,
             const float* __restrict__ W1, unsigned* __restrict__ out32)
{
    extern __shared__ __half smh[];
    __half* A = smh;
    __half* B = smh + 64*ASTR;
    int tid = threadIdx.x, w = tid>>5, L = tid&31;
    int wm = w >> 1, wn = w & 1;

    const float* Wc = W1 + 2*131*64;
    for (int i = tid; i < 128*64; i += 256) {
        int k = i >> 6, n = i & 63;
        B[k*B1STR + n] = __float2half_rn(Wc[k*64 + n]);
    }
    __syncthreads();

    int r = L >> 2, cq = (L & 3) * 2;
    for (int tile = blockIdx.x; tile < BN/64; tile += gridDim.x) {
        int pt0 = tile * 64;
        for (int i = tid; i < 64*64; i += 256) {
            int p = i >> 6, c2 = i & 63;
            float2 v = (c2 < 32) ? *(const float2*)&s0[(size_t)(pt0+p)*64 + 2*c2]
                                 : *(const float2*)&s1[(size_t)(pt0+p)*64 + 2*(c2-32)];
            *(__half2*)&A[p*ASTR + 2*c2] = __floats2half2_rn(v.x, v.y);
        }
        __syncthreads();

        float C[4][4];
        #pragma unroll
        for (int i = 0; i < 4; i++)
            #pragma unroll
            for (int j = 0; j < 4; j++) C[i][j] = 0.f;

        #pragma unroll
        for (int ks = 0; ks < 8; ks++) {
            int k0 = ks * 16;
            unsigned a0,a1,a2,a3;
            ldsm_x4(a0,a1,a2,a3, sm_u32(&A[(wm*16 + (L&15))*ASTR + k0 + (L>>4)*8]));
            #pragma unroll
            for (int nt = 0; nt < 2; nt++) {
                unsigned b0,b1,b2,b3;
                ldsm_x4_t(b0,b1,b2,b3,
                    sm_u32(&B[(k0 + (L&15))*B1STR + wn*32 + nt*16 + (L>>4)*8]));
                mma16816(C[2*nt],   a0,a1,a2,a3, b0,b1);
                mma16816(C[2*nt+1], a0,a1,a2,a3, b2,b3);
            }
        }
        #pragma unroll
        for (int nt8 = 0; nt8 < 4; nt8++) {
            int col = wn*32 + nt8*8 + cq;
            int p = pt0 + wm*16 + r;
            __half2 lo = __floats2half2_rn(C[nt8][0], C[nt8][1]);
            __half2 hi = __floats2half2_rn(C[nt8][2], C[nt8][3]);
            out32[(size_t)p*32 + (col>>1)]     = *(const unsigned*)&lo;
            out32[(size_t)(p+8)*32 + (col>>1)] = *(const unsigned*)&hi;
        }
        __syncthreads();
    }
}

// ---------------- gate01 (HMMA MLP): branches 0+1 -> z, r*h ----------------
// tile = 64 points, 8 warps: single-point gather (R14-proven), HMMA MLP.
__global__ void __launch_bounds__(256)
gate01_hmma(const float* __restrict__ h,
    const float* __restrict__ W1, const float* __restrict__ b1,
    const float* __restrict__ W2, const float* __restrict__ b2,
    const float* __restrict__ W3, const float* __restrict__ b3,
    const int* __restrict__ nidx, const float* __restrict__ ef,
    float* __restrict__ z_out, float* __restrict__ rh_out)
{
    extern __shared__ __half smh[];
    __half* sW2 = smh;                 // 2 x [64 x PSTR]
    __half* sW3 = smh + 2*64*PSTR;     // 2 x [64 x PSTR]
    __half* P   = smh + 4*64*PSTR;     // 2 x [64 x PSTR]  (PA, PB)
    uint2* mt_all = (uint2*)(smh + 6*64*PSTR);  // 8 warps x 32 uint2
    int tid = threadIdx.x, w = tid>>5, L = tid&31;

    for (int i = tid; i < 2*64*64; i += 256) {
        int br = i >> 12, rem = i & 4095, j = rem >> 6, d = rem & 63;
        sW2[br*64*PSTR + j*PSTR + d] = __float2half_rn(W2[br*4096 + j*64 + d]);
        sW3[br*64*PSTR + j*PSTR + d] = __float2half_rn(W3[br*4096 + j*64 + d]);
    }
    __syncthreads();

    const float* eWa = W1 + 128*64;
    const float* eWb = W1 + 131*64 + 128*64;
    __half2 wA[3], wB[3];
    #pragma unroll
    for (int j = 0; j < 3; j++) {
        wA[j] = __floats2half2_rn(eWa[j*64 + 2*L], eWa[j*64 + 2*L + 1]);
        wB[j] = __floats2half2_rn(eWb[j*64 + 2*L], eWb[j*64 + 2*L + 1]);
    }
    float2 b1a = *(const float2*)&b1[2*L], b1b = *(const float2*)&b1[64 + 2*L];

    int pt0 = blockIdx.x * 64;
    int bb = pt0 >> 13;
    const uint2* Fab = g_F1ab + (size_t)bb*NN*32;
    __half* PA = P;
    __half* PB = P + 64*PSTR;
    uint2* mt = mt_all + w*32;

    // ---- phase 1: gather + pool (single point per round) ----
    for (int qq = 0; qq < 8; qq++) {
        int pl = w*8 + qq;
        int p  = pt0 + pl;
        {
            int fi = nidx[(size_t)p*KK + L];
            const float* ep = ef + (size_t)p*96 + 3*L;
            __half2 e01 = __floats2half2_rn(ep[0], ep[1]);
            unsigned e2b = (unsigned)__half_as_ushort(__float2half_rn(ep[2]));
            mt[L] = make_uint2((unsigned)fi | (e2b << 16), *(const unsigned*)&e01);
        }
        __syncwarp();
        __half2 ma = __float2half2_rn(-6.0e4f), mb = ma;
        #pragma unroll 8
        for (int k = 0; k < KK; k++) {
            uint2 m = mt[k];
            int fi = (int)(m.x & 0xFFFFu);
            __half2 h2v = __half2half2(__ushort_as_half((unsigned short)(m.x >> 16)));
            __half2 e01 = *(const __half2*)&m.y;
            __half2 h0 = __low2half2(e01), h1 = __high2half2(e01);
            uint2 v = __ldg(&Fab[(size_t)fi*32 + L]);
            __half2 ta = *(const __half2*)&v.x;
            ta = __hfma2(h0, wA[0], ta);
            ta = __hfma2(h1, wA[1], ta);
            ta = __hfma2(h2v, wA[2], ta);
            ma = __hmax2(ma, ta);
            __half2 tb = *(const __half2*)&v.y;
            tb = __hfma2(h0, wB[0], tb);
            tb = __hfma2(h1, wB[1], tb);
            tb = __hfma2(h2v, wB[2], tb);
            mb = __hmax2(mb, tb);
        }
        __syncwarp();
        float2 fa = __half22float2(ma), fb = __half22float2(mb);
        fa.x = lrelu(fa.x + b1a.x);  fa.y = lrelu(fa.y + b1a.y);
        fb.x = lrelu(fb.x + b1b.x);  fb.y = lrelu(fb.y + b1b.y);
        *(__half2*)&PA[pl*PSTR + 2*L] = __floats2half2_rn(fa.x, fa.y);
        *(__half2*)&PB[pl*PSTR + 2*L] = __floats2half2_rn(fb.x, fb.y);
    }
    __syncthreads();

    // ---- phase 2: MLP on tensor pipe ----
    int wbr = w >> 2, wm = w & 3;        // 4 m-warps per branch
    __half* Pb  = P   + wbr*64*PSTR;
    __half* W2b = sW2 + wbr*64*PSTR;
    __half* W3b = sW3 + wbr*64*PSTR;
    int r = L >> 2, cq = (L & 3) * 2;
    const float* b2v = b2 + wbr*64;
    const float* b3v = b3 + wbr*64;

    // layer 1
    float C[8][4];
    #pragma unroll
    for (int i = 0; i < 8; i++)
        #pragma unroll
        for (int j = 0; j < 4; j++) C[i][j] = 0.f;
    #pragma unroll
    for (int ks = 0; ks < 4; ks++) {
        int k0 = ks * 16;
        unsigned a0,a1,a2,a3;
        ldsm_x4(a0,a1,a2,a3, sm_u32(&Pb[(wm*16 + (L&15))*PSTR + k0 + (L>>4)*8]));
        #pragma unroll
        for (int nt = 0; nt < 4; nt++) {
            unsigned b0v,b1v,b2q,b3q;
            ldsm_x4_t(b0v,b1v,b2q,b3q,
                sm_u32(&W2b[(k0 + (L&15))*PSTR + nt*16 + (L>>4)*8]));
            mma16816(C[2*nt],   a0,a1,a2,a3, b0v,b1v);
            mma16816(C[2*nt+1], a0,a1,a2,a3, b2q,b3q);
        }
    }
    __syncthreads();   // all ldsm of P complete -> safe to overwrite
    #pragma unroll
    for (int nt8 = 0; nt8 < 8; nt8++) {
        int col = nt8*8 + cq;
        float c0 = lrelu(C[nt8][0] + __ldg(&b2v[col]));
        float c1 = lrelu(C[nt8][1] + __ldg(&b2v[col+1]));
        float c2 = lrelu(C[nt8][2] + __ldg(&b2v[col]));
        float c3 = lrelu(C[nt8][3] + __ldg(&b2v[col+1]));
        *(__half2*)&Pb[(wm*16 + r)*PSTR + col]     = __floats2half2_rn(c0, c1);
        *(__half2*)&Pb[(wm*16 + r + 8)*PSTR + col] = __floats2half2_rn(c2, c3);
    }
    __syncthreads();

    // layer 2
    #pragma unroll
    for (int i = 0; i < 8; i++)
        #pragma unroll
        for (int j = 0; j < 4; j++) C[i][j] = 0.f;
    #pragma unroll
    for (int ks = 0; ks < 4; ks++) {
        int k0 = ks * 16;
        unsigned a0,a1,a2,a3;
        ldsm_x4(a0,a1,a2,a3, sm_u32(&Pb[(wm*16 + (L&15))*PSTR + k0 + (L>>4)*8]));
        #pragma unroll
        for (int nt = 0; nt < 4; nt++) {
            unsigned b0v,b1v,b2q,b3q;
            ldsm_x4_t(b0v,b1v,b2q,b3q,
                sm_u32(&W3b[(k0 + (L&15))*PSTR + nt*16 + (L>>4)*8]));
            mma16816(C[2*nt],   a0,a1,a2,a3, b0v,b1v);
            mma16816(C[2*nt+1], a0,a1,a2,a3, b2q,b3q);
        }
    }
    // final epilogue
    #pragma unroll
    for (int nt8 = 0; nt8 < 8; nt8++) {
        int col = nt8*8 + cq;
        int pLo = pt0 + wm*16 + r;
        int pHi = pLo + 8;
        float c0 = sigm(C[nt8][0] + __ldg(&b3v[col]));
        float c1 = sigm(C[nt8][1] + __ldg(&b3v[col+1]));
        float c2 = sigm(C[nt8][2] + __ldg(&b3v[col]));
        float c3 = sigm(C[nt8][3] + __ldg(&b3v[col+1]));
        if (wbr == 0) {
            *(float2*)&z_out[(size_t)pLo*64 + col] = make_float2(c0, c1);
            *(float2*)&z_out[(size_t)pHi*64 + col] = make_float2(c2, c3);
        } else {
            float2 hLo = *(const float2*)&h[(size_t)pLo*64 + col];
            float2 hHi = *(const float2*)&h[(size_t)pHi*64 + col];
            *(float2*)&rh_out[(size_t)pLo*64 + col] = make_float2(c0*hLo.x, c1*hLo.y);
            *(float2*)&rh_out[(size_t)pHi*64 + col] = make_float2(c2*hHi.x, c3*hHi.y);
        }
    }
}

// ---------------- gate2 (HMMA MLP): branch 2 -> q; out = h + z*(q-h) ----------------
// tile = 64 points, 8 warps: gather 8 pts/warp (4-pt interleaved), MLP 4x2.
__global__ void __launch_bounds__(256)
gate2_hmma(const float* __restrict__ h,
    const float* __restrict__ W1, const float* __restrict__ b1,
    const float* __restrict__ W2, const float* __restrict__ b2,
    const float* __restrict__ W3, const float* __restrict__ b3,
    const int* __restrict__ nidx, const float* __restrict__ ef,
    float* __restrict__ out)
{
    extern __shared__ __half smh[];
    __half* sW2 = smh;                 // [64 x PSTR]
    __half* sW3 = smh + 64*PSTR;       // [64 x PSTR]
    __half* P   = smh + 2*64*PSTR;     // [64 x PSTR]
    uint2* mt_all = (uint2*)(smh + 3*64*PSTR);  // 8 warps x 128 uint2
    int tid = threadIdx.x, w = tid>>5, L = tid&31;

    for (int i = tid; i < 64*64; i += 256) {
        int j = i >> 6, d = i & 63;
        sW2[j*PSTR + d] = __float2half_rn(W2[2*4096 + j*64 + d]);
        sW3[j*PSTR + d] = __float2half_rn(W3[2*4096 + j*64 + d]);
    }
    __syncthreads();

    const float* eWc = W1 + 2*131*64 + 128*64;
    __half2 wC[3];
    #pragma unroll
    for (int j = 0; j < 3; j++)
        wC[j] = __floats2half2_rn(eWc[j*64 + 2*L], eWc[j*64 + 2*L + 1]);
    float2 b1c = *(const float2*)&b1[128 + 2*L];

    int pt0 = blockIdx.x * 64;
    int bb = pt0 >> 13;
    const __half2* Fc = g_F1c + (size_t)bb*NN*32;
    uint2* mtw = mt_all + w*128;

    // ---- phase 1: gather + pool, 4 points interleaved ----
    for (int qq = 0; qq < 2; qq++) {
        int plb = w*8 + 4*qq;
        #pragma unroll
        for (int j = 0; j < 4; j++) {
            int p = pt0 + plb + j;
            int fi = nidx[(size_t)p*KK + L];
            const float* ep = ef + (size_t)p*96 + 3*L;
            __half2 e01 = __floats2half2_rn(ep[0], ep[1]);
            unsigned e2b = (unsigned)__half_as_ushort(__float2half_rn(ep[2]));
            mtw[j*32 + L] = make_uint2((unsigned)fi | (e2b << 16), *(const unsigned*)&e01);
        }
        __syncwarp();
        __half2 mc[4];
        #pragma unroll
        for (int j = 0; j < 4; j++) mc[j] = __float2half2_rn(-6.0e4f);
        #pragma unroll 4
        for (int k = 0; k < KK; k++) {
            uint2 m[4];
            __half2 v[4];
            #pragma unroll
            for (int j = 0; j < 4; j++) m[j] = mtw[j*32 + k];
            #pragma unroll
            for (int j = 0; j < 4; j++)
                v[j] = __ldg(&Fc[(size_t)(m[j].x & 0xFFFFu)*32 + L]);
            #pragma unroll
            for (int j = 0; j < 4; j++) {
                __half2 h2v = __half2half2(__ushort_as_half((unsigned short)(m[j].x >> 16)));
                __half2 e01 = *(const __half2*)&m[j].y;
                __half2 h0 = __low2half2(e01), h1 = __high2half2(e01);
                __half2 t = v[j];
                t = __hfma2(h0, wC[0], t);
                t = __hfma2(h1, wC[1], t);
                t = __hfma2(h2v, wC[2], t);
                mc[j] = __hmax2(mc[j], t);
            }
        }
        __syncwarp();
        #pragma unroll
        for (int j = 0; j < 4; j++) {
            float2 fc = __half22float2(mc[j]);
            fc.x = lrelu(fc.x + b1c.x);  fc.y = lrelu(fc.y + b1c.y);
            *(__half2*)&P[(plb + j)*PSTR + 2*L] = __floats2half2_rn(fc.x, fc.y);
        }
    }
    __syncthreads();

    // ---- phase 2: MLP (M=64, 4 m-bands x 2 n-halves over 8 warps) ----
    int wm = w >> 1, wn = w & 1;
    int r = L >> 2, cq = (L & 3) * 2;
    const float* b2v = b2 + 128;
    const float* b3v = b3 + 128;

    float C[4][4];
    #pragma unroll
    for (int i = 0; i < 4; i++)
        #pragma unroll
        for (int j = 0; j < 4; j++) C[i][j] = 0.f;
    #pragma unroll
    for (int ks = 0; ks < 4; ks++) {
        int k0 = ks * 16;
        unsigned a0,a1,a2,a3;
        ldsm_x4(a0,a1,a2,a3, sm_u32(&P[(wm*16 + (L&15))*PSTR + k0 + (L>>4)*8]));
        #pragma unroll
        for (int nt = 0; nt < 2; nt++) {
            unsigned b0v,b1v,b2q,b3q;
            ldsm_x4_t(b0v,b1v,b2q,b3q,
                sm_u32(&sW2[(k0 + (L&15))*PSTR + wn*32 + nt*16 + (L>>4)*8]));
            mma16816(C[2*nt],   a0,a1,a2,a3, b0v,b1v);
            mma16816(C[2*nt+1], a0,a1,a2,a3, b2q,b3q);
        }
    }
    __syncthreads();
    #pragma unroll
    for (int nt4 = 0; nt4 < 4; nt4++) {
        int col = wn*32 + nt4*8 + cq;
        float c0 = lrelu(C[nt4][0] + __ldg(&b2v[col]));
        float c1 = lrelu(C[nt4][1] + __ldg(&b2v[col+1]));
        float c2 = lrelu(C[nt4][2] + __ldg(&b2v[col]));
        float c3 = lrelu(C[nt4][3] + __ldg(&b2v[col+1]));
        *(__half2*)&P[(wm*16 + r)*PSTR + col]     = __floats2half2_rn(c0, c1);
        *(__half2*)&P[(wm*16 + r + 8)*PSTR + col] = __floats2half2_rn(c2, c3);
    }
    __syncthreads();

    #pragma unroll
    for (int i = 0; i < 4; i++)
        #pragma unroll
        for (int j = 0; j < 4; j++) C[i][j] = 0.f;
    #pragma unroll
    for (int ks = 0; ks < 4; ks++) {
        int k0 = ks * 16;
        unsigned a0,a1,a2,a3;
        ldsm_x4(a0,a1,a2,a3, sm_u32(&P[(wm*16 + (L&15))*PSTR + k0 + (L>>4)*8]));
        #pragma unroll
        for (int nt = 0; nt < 2; nt++) {
            unsigned b0v,b1v,b2q,b3q;
            ldsm_x4_t(b0v,b1v,b2q,b3q,
                sm_u32(&sW3[(k0 + (L&15))*PSTR + wn*32 + nt*16 + (L>>4)*8]));
            mma16816(C[2*nt],   a0,a1,a2,a3, b0v,b1v);
            mma16816(C[2*nt+1], a0,a1,a2,a3, b2q,b3q);
        }
    }
    #pragma unroll
    for (int nt4 = 0; nt4 < 4; nt4++) {
        int col = wn*32 + nt4*8 + cq;
        int pLo = pt0 + wm*16 + r;
        int pHi = pLo + 8;
        float q0 = tanhf(C[nt4][0] + __ldg(&b3v[col]));
        float q1 = tanhf(C[nt4][1] + __ldg(&b3v[col+1]));
        float q2 = tanhf(C[nt4][2] + __ldg(&b3v[col]));
        float q3 = tanhf(C[nt4][3] + __ldg(&b3v[col+1]));
        float2 zLo = *(const float2*)&g_z[(size_t)pLo*64 + col];
        float2 zHi = *(const float2*)&g_z[(size_t)pHi*64 + col];
        float2 hLo = *(const float2*)&h[(size_t)pLo*64 + col];
        float2 hHi = *(const float2*)&h[(size_t)pHi*64 + col];
        *(float2*)&out[(size_t)pLo*64 + col] =
            make_float2(hLo.x + zLo.x*(q0 - hLo.x), hLo.y + zLo.y*(q1 - hLo.y));
        *(float2*)&out[(size_t)pHi*64 + col] =
            make_float2(hHi.x + zHi.x*(q2 - hHi.x), hHi.y + zHi.y*(q3 - hHi.y));
    }
}

extern "C" void kernel_launch(void* const* d_in, const int* in_sizes, int n_in,
                              void* d_out, int out_size)
{
    const float* h   = (const float*)d_in[0];
    const float* x   = (const float*)d_in[1];
    // d_in[2] = c, unused (matches reference)
    const float* W1  = (const float*)d_in[3];
    const float* b1  = (const float*)d_in[4];
    const float* W2  = (const float*)d_in[5];
    const float* b2  = (const float*)d_in[6];
    const float* W3  = (const float*)d_in[7];
    const float* b3  = (const float*)d_in[8];
    const int*   nidx = (const int*)d_in[9];
    const float* ef  = (const float*)d_in[10];
    float* out = (float*)d_out;

    void *pF1ab, *pF1c, *pz, *prh;
    cudaGetSymbolAddress(&pF1ab, g_F1ab);
    cudaGetSymbolAddress(&pF1c,  g_F1c);
    cudaGetSymbolAddress(&pz,    g_z);
    cudaGetSymbolAddress(&prh,   g_rh);

    const int smem_l2h = (64*ASTR + 128*B2STR) * 2;        // 52224 B
    const int smem_l1h = (64*ASTR + 128*B1STR) * 2;        // 35840 B
    const int smem_g01 = 6*64*PSTR*2 + 8*32*8;             // 57344 B
    const int smem_g2  = 3*64*PSTR*2 + 8*128*8;            // 35840 B

    cudaFuncSetAttribute(linear2_hmma, cudaFuncAttributeMaxDynamicSharedMemorySize, smem_l2h);
    cudaFuncSetAttribute(linear1_hmma, cudaFuncAttributeMaxDynamicSharedMemorySize, smem_l1h);
    cudaFuncSetAttribute(gate01_hmma,  cudaFuncAttributeMaxDynamicSharedMemorySize, smem_g01);
    cudaFuncSetAttribute(gate2_hmma,   cudaFuncAttributeMaxDynamicSharedMemorySize, smem_g2);

    dim3 blk(256);

    // F1ab = [h|x] @ {W1a[0], W1a[1]}  (HMMA, packed fp16 out)
    linear2_hmma<<<296, blk, smem_l2h>>>(h, x, W1, (unsigned*)pF1ab);
    // z, r*h  (512 tiles of 64 points)
    gate01_hmma<<<512, blk, smem_g01>>>(h, W1, b1, W2, b2, W3, b3, nidx, ef,
                                        (float*)pz, (float*)prh);
    // F1c = [r*h|x] @ W1a[2]  (HMMA, fp16 out)
    linear1_hmma<<<296, blk, smem_l1h>>>((const float*)prh, x, W1, (unsigned*)pF1c);
    // q and final output  (512 tiles of 64 points)
    gate2_hmma<<<512, blk, smem_g2>>>(h, W1, b1, W2, b2, W3, b3, nidx, ef, out);
}